// round 8
// baseline (speedup 1.0000x reference)
#include <cuda_runtime.h>

// MatchNet: per-row MLP(6->20->20->20->8, tanh) + 150-iter PDHG LP.
// R8: fma-pipe-occupancy attack. FFMA with immediate multiplier has
// rt_SMSP=1 vs 2 for 3-reg FFMA/FADD (HW-measured). ssd-carry makes every
// loop FMA constant-multiplier; adds become fma(a, 1.0_imm, b) via PTX.

#define NTHREADS 32
#define PDHG_ITERS 150

#define TAU  0.18898223650461357f   /* 1/sqrt(28) */
#define TCC  1.8898223650461357f    /* tau * control_strength(10) */
#define SG2  0.37796447300922714f   /* 2*sigma */

typedef unsigned long long u64;

__device__ __forceinline__ u64 pk(float a, float b) {
    u64 r; asm("mov.b64 %0, {%1, %2};" : "=l"(r) : "f"(a), "f"(b)); return r;
}
__device__ __forceinline__ void upk(float& a, float& b, u64 p) {
    asm("mov.b64 {%0, %1}, %2;" : "=f"(a), "=f"(b) : "l"(p));
}
__device__ __forceinline__ u64 fma2(u64 a, u64 b, u64 c) {
    u64 d; asm("fma.rn.f32x2 %0, %1, %2, %3;" : "=l"(d) : "l"(a), "l"(b), "l"(c)); return d;
}

// a + b as FFMA-imm (multiplier = 1.0f exact): rt 1 on the fma pipe.
__device__ __forceinline__ float fai(float a, float b) {
    float r;
    asm("fma.rn.f32 %0, %1, 0f3F800000, %2;" : "=f"(r) : "f"(a), "f"(b));
    return r;
}

__device__ __forceinline__ float fast_rsqrt(float v) {
    float r; asm("rsqrt.approx.f32 %0, %1;" : "=f"(r) : "f"(v)); return r;
}
__device__ __forceinline__ float fast_tanh(float x) {
    float e = __expf(2.0f * x);
    return 1.0f - __fdividef(2.0f, e + 1.0f);
}

__global__ __launch_bounds__(NTHREADS)
void matchnet_kernel(
    const float* __restrict__ X,
    const float* __restrict__ W1, const float* __restrict__ b1,
    const float* __restrict__ W2, const float* __restrict__ b2,
    const float* __restrict__ W3, const float* __restrict__ b3,
    const float* __restrict__ W4, const float* __restrict__ b4,
    float* __restrict__ out, int B)
{
    __shared__ __align__(16) float sW1[120], sW2[400], sW3[400], sW4[160];
    __shared__ __align__(16) float sb1[20], sb2[20], sb3[20], sb4[8];

    const int t = threadIdx.x;
    for (int i = t; i < 120; i += NTHREADS) sW1[i] = W1[i];
    for (int i = t; i < 400; i += NTHREADS) sW2[i] = W2[i];
    for (int i = t; i < 400; i += NTHREADS) sW3[i] = W3[i];
    for (int i = t; i < 160; i += NTHREADS) sW4[i] = W4[i];
    if (t < 20) { sb1[t] = b1[t]; sb2[t] = b2[t]; sb3[t] = b3[t]; }
    if (t < 8)  { sb4[t] = b4[t]; }
    __syncthreads();

    const int row = blockIdx.x * NTHREADS + t;
    if (row >= B) return;

    // ---- input row (RHS b of the LP) ----
    float Z[6];
    {
        const float2* p = (const float2*)(X + row * 6);
        float2 a0 = p[0], a1 = p[1], a2 = p[2];
        Z[0] = a0.x; Z[1] = a0.y; Z[2] = a1.x;
        Z[3] = a1.y; Z[4] = a2.x; Z[5] = a2.y;
    }

    // ---- MLP, f32x2-packed (validated R6; off the dominant loop) ----
    float h[20], h2[20];
    {
        u64 a[10];
#pragma unroll
        for (int jp = 0; jp < 10; jp++) a[jp] = *(const u64*)&sb1[2 * jp];
#pragma unroll
        for (int k = 0; k < 6; k++) {
            u64 zz = pk(Z[k], Z[k]);
#pragma unroll
            for (int jp = 0; jp < 10; jp++)
                a[jp] = fma2(zz, *(const u64*)&sW1[k * 20 + 2 * jp], a[jp]);
        }
#pragma unroll
        for (int jp = 0; jp < 10; jp++) {
            float s0, s1; upk(s0, s1, a[jp]);
            h[2 * jp] = fast_tanh(s0); h[2 * jp + 1] = fast_tanh(s1);
        }
    }
    {
        u64 a[10];
#pragma unroll
        for (int jp = 0; jp < 10; jp++) a[jp] = *(const u64*)&sb2[2 * jp];
#pragma unroll
        for (int k = 0; k < 20; k++) {
            u64 hh = pk(h[k], h[k]);
#pragma unroll
            for (int jp = 0; jp < 10; jp++)
                a[jp] = fma2(hh, *(const u64*)&sW2[k * 20 + 2 * jp], a[jp]);
        }
#pragma unroll
        for (int jp = 0; jp < 10; jp++) {
            float s0, s1; upk(s0, s1, a[jp]);
            h2[2 * jp] = fast_tanh(s0); h2[2 * jp + 1] = fast_tanh(s1);
        }
    }
    {
        u64 a[10];
#pragma unroll
        for (int jp = 0; jp < 10; jp++) a[jp] = *(const u64*)&sb3[2 * jp];
#pragma unroll
        for (int k = 0; k < 20; k++) {
            u64 hh = pk(h2[k], h2[k]);
#pragma unroll
            for (int jp = 0; jp < 10; jp++)
                a[jp] = fma2(hh, *(const u64*)&sW3[k * 20 + 2 * jp], a[jp]);
        }
#pragma unroll
        for (int jp = 0; jp < 10; jp++) {
            float s0, s1; upk(s0, s1, a[jp]);
            h[2 * jp] = fast_tanh(s0); h[2 * jp + 1] = fast_tanh(s1);
        }
    }
    float z[8];
    {
        u64 a[4];
#pragma unroll
        for (int jp = 0; jp < 4; jp++) a[jp] = *(const u64*)&sb4[2 * jp];
#pragma unroll
        for (int k = 0; k < 20; k++) {
            u64 hh = pk(h[k], h[k]);
#pragma unroll
            for (int jp = 0; jp < 4; jp++)
                a[jp] = fma2(hh, *(const u64*)&sW4[k * 8 + 2 * jp], a[jp]);
        }
#pragma unroll
        for (int jp = 0; jp < 4; jp++) upk(z[2 * jp], z[2 * jp + 1], a[jp]);
    }

    // ---- PDHG per-row constants ----
    // kc_i = sigma*(Sz_i - Z_i), nc4_j = -sigma*z_j
    float kc[6];
    {
        float p02 = z[0] + z[2], p57 = z[5] + z[7], p13 = z[1] + z[3];
        float p01 = z[0] + z[1], p23 = z[2] + z[3], p12 = z[1] + z[2];
        float p47 = z[4] + z[7], p04 = z[0] + z[4];
        kc[0] = TAU * ((p02 + p57) - Z[0]);
        kc[1] = TAU * ((p13 + z[4]) - Z[1]);
        kc[2] = TAU * ((p01 + z[6]) - Z[2]);
        kc[3] = TAU * ((p23 + z[5]) - Z[3]);
        kc[4] = TAU * ((p12 + p47) - Z[4]);
        kc[5] = TAU * ((p04 + z[6]) - Z[5]);
    }
    float nc4[8];
#pragma unroll
    for (int j = 0; j < 8; j++) nc4[j] = -TAU * z[j];
    const float tauReg = TAU;
    const float oneReg = 1.0f;

    // ---- state init (equivalent to validated R7 prologue) ----
    // sd0 = max(z,0) - z ; ssd_prev (sp) = sd0 (scale_prev = 1) ;
    // Sssd_prev (Sp) = S*sd0 ; e = sd0 + tau (yi0 = 0) ;
    // y = max(0, sigma*Sp + kc) ; yi = 0.
    float e[8], sp[8], Sp[6], y[6], yi[8];
    {
        float sd[8];
#pragma unroll
        for (int j = 0; j < 8; j++) {
            sd[j] = fmaxf(z[j], 0.0f) - z[j];
            sp[j] = sd[j];
            e[j]  = sd[j] + TAU;
            yi[j] = 0.0f;
        }
        float p02 = sd[0] + sd[2], p57 = sd[5] + sd[7], p13 = sd[1] + sd[3];
        float p01 = sd[0] + sd[1], p23 = sd[2] + sd[3], p12 = sd[1] + sd[2];
        float p47 = sd[4] + sd[7], p04 = sd[0] + sd[4];
        Sp[0] = p02 + p57; Sp[1] = p13 + sd[4]; Sp[2] = p01 + sd[6];
        Sp[3] = p23 + sd[5]; Sp[4] = p12 + p47; Sp[5] = p04 + sd[6];
#pragma unroll
        for (int i = 0; i < 6; i++)
            y[i] = fmaxf(0.0f, fmaf(TAU, Sp[i], kc[i]));
    }

    float ssd0, ssd1, ssd2, ssd3, ssd4, ssd5, ssd6, ssd7;  // live after loop

#pragma unroll 2
    for (int it = 0; it < PDHG_ITERS; it++) {
        // ---- head: sy = S^T-row sums of y (fai = FFMA-imm adds) ----
        float q25 = fai(y[2], y[5]), q04 = fai(y[0], y[4]), q14 = fai(y[1], y[4]);
        float sy0 = fai(y[0], q25);
        float sy1 = fai(q14, y[2]);
        float sy2 = fai(q04, y[3]);
        float sy3 = fai(y[1], y[3]);
        float sy4 = fai(q14, y[5]);
        float sy5 = fai(y[0], y[3]);
        // sy6 = q25, sy7 = q04

        // d = e - tau*sy  (constant multiplier -> FFMA-imm)
        float d0 = fmaf(-TAU, sy0, e[0]);
        float d1 = fmaf(-TAU, sy1, e[1]);
        float d2 = fmaf(-TAU, sy2, e[2]);
        float d3 = fmaf(-TAU, sy3, e[3]);
        float d4 = fmaf(-TAU, sy4, e[4]);
        float d5 = fmaf(-TAU, sy5, e[5]);
        float d6 = fmaf(-TAU, q25, e[6]);
        float d7 = fmaf(-TAU, q04, e[7]);

        // ||d||^2 tree + rsqrt (nn=0 -> rr=inf -> scale=0, exact)
        float p0 = fmaf(d0, d0, d1 * d1);
        float p1 = fmaf(d2, d2, d3 * d3);
        float p2 = fmaf(d4, d4, d5 * d5);
        float p3 = fmaf(d6, d6, d7 * d7);
        float nn = fai(fai(p0, p1), fai(p2, p3));
        float rr = fast_rsqrt(nn);

        // ---- rsqrt shadow: pre-scale dual halves (old y/yi, carried sp/Sp)
        // t1_j = (yi_j + nc4_j) + sigma*sp_j ; t2_i = (y_i + kc_i) - sigma*Sp_i
        float t1[8];
#pragma unroll
        for (int j = 0; j < 8; j++)
            t1[j] = fmaf(TAU, sp[j], fai(yi[j], nc4[j]));
        float t2[6];
#pragma unroll
        for (int i = 0; i < 6; i++)
            t2[i] = fmaf(-TAU, Sp[i], fai(y[i], kc[i]));

        // ---- scale = max(0, 1 - tc*rr) ----
        float scale = fmaxf(0.0f, fmaf(-TCC, rr, oneReg));

        // ---- ssd = scale*d (the only runtime-scalar multiplies) ----
        ssd0 = scale * d0; ssd1 = scale * d1;
        ssd2 = scale * d2; ssd3 = scale * d3;
        ssd4 = scale * d4; ssd5 = scale * d5;
        ssd6 = scale * d6; ssd7 = scale * d7;

        // ---- Sssd = S * ssd (fai gathers) ----
        float f02 = fai(ssd0, ssd2), f57 = fai(ssd5, ssd7), f13 = fai(ssd1, ssd3);
        float f01 = fai(ssd0, ssd1), f23 = fai(ssd2, ssd3), f12 = fai(ssd1, ssd2);
        float f47 = fai(ssd4, ssd7), f04 = fai(ssd0, ssd4);
        float Ss0 = fai(f02, f57), Ss1 = fai(f13, ssd4), Ss2 = fai(f01, ssd6);
        float Ss3 = fai(f23, ssd5), Ss4 = fai(f12, f47), Ss5 = fai(f04, ssd6);

        // ---- dual updates (constant multipliers) ----
        y[0] = fmaxf(0.0f, fmaf(SG2, Ss0, t2[0]));
        y[1] = fmaxf(0.0f, fmaf(SG2, Ss1, t2[1]));
        y[2] = fmaxf(0.0f, fmaf(SG2, Ss2, t2[2]));
        y[3] = fmaxf(0.0f, fmaf(SG2, Ss3, t2[3]));
        y[4] = fmaxf(0.0f, fmaf(SG2, Ss4, t2[4]));
        y[5] = fmaxf(0.0f, fmaf(SG2, Ss5, t2[5]));

        yi[0] = fmaxf(0.0f, fmaf(-SG2, ssd0, t1[0]));
        yi[1] = fmaxf(0.0f, fmaf(-SG2, ssd1, t1[1]));
        yi[2] = fmaxf(0.0f, fmaf(-SG2, ssd2, t1[2]));
        yi[3] = fmaxf(0.0f, fmaf(-SG2, ssd3, t1[3]));
        yi[4] = fmaxf(0.0f, fmaf(-SG2, ssd4, t1[4]));
        yi[5] = fmaxf(0.0f, fmaf(-SG2, ssd5, t1[5]));
        yi[6] = fmaxf(0.0f, fmaf(-SG2, ssd6, t1[6]));
        yi[7] = fmaxf(0.0f, fmaf(-SG2, ssd7, t1[7]));

        // ---- e = (ssd + tau) + tau*yi_new ----
        e[0] = fmaf(TAU, yi[0], fai(ssd0, tauReg));
        e[1] = fmaf(TAU, yi[1], fai(ssd1, tauReg));
        e[2] = fmaf(TAU, yi[2], fai(ssd2, tauReg));
        e[3] = fmaf(TAU, yi[3], fai(ssd3, tauReg));
        e[4] = fmaf(TAU, yi[4], fai(ssd4, tauReg));
        e[5] = fmaf(TAU, yi[5], fai(ssd5, tauReg));
        e[6] = fmaf(TAU, yi[6], fai(ssd6, tauReg));
        e[7] = fmaf(TAU, yi[7], fai(ssd7, tauReg));

        // ---- carry ----
        sp[0] = ssd0; sp[1] = ssd1; sp[2] = ssd2; sp[3] = ssd3;
        sp[4] = ssd4; sp[5] = ssd5; sp[6] = ssd6; sp[7] = ssd7;
        Sp[0] = Ss0; Sp[1] = Ss1; Sp[2] = Ss2;
        Sp[3] = Ss3; Sp[4] = Ss4; Sp[5] = Ss5;
    }

    // ---- x = z + ssd ----
    float4* p = (float4*)(out + row * 8);
    p[0] = make_float4(z[0] + ssd0, z[1] + ssd1, z[2] + ssd2, z[3] + ssd3);
    p[1] = make_float4(z[4] + ssd4, z[5] + ssd5, z[6] + ssd6, z[7] + ssd7);
}

extern "C" void kernel_launch(void* const* d_in, const int* in_sizes, int n_in,
                              void* d_out, int out_size) {
    const float* X  = (const float*)d_in[0];
    const float* W1 = (const float*)d_in[1];
    const float* b1 = (const float*)d_in[2];
    const float* W2 = (const float*)d_in[3];
    const float* b2 = (const float*)d_in[4];
    const float* W3 = (const float*)d_in[5];
    const float* b3 = (const float*)d_in[6];
    const float* W4 = (const float*)d_in[7];
    const float* b4 = (const float*)d_in[8];

    const int B = in_sizes[0] / 6;
    const int grid = (B + NTHREADS - 1) / NTHREADS;
    matchnet_kernel<<<grid, NTHREADS>>>(X, W1, b1, W2, b2, W3, b3, W4, b4,
                                        (float*)d_out, B);
}

// round 9
// speedup vs baseline: 1.0818x; 1.0818x over previous
#include <cuda_runtime.h>

// MatchNet: per-row MLP(6->20->20->20->8, tanh) + 150-iter PDHG LP.
// R9: minimal-op PDHG body (95 fma-class ops/iter vs 109 in R7/R8):
//  - YIp = yI + 1 state: yI update = fmax(1.0, fma(-sigma, xb, YIp)),
//    and gy = S^T y6 - YIp = g - 1 so d = fma(-tau, gy, sdn) directly
//    (sdt/e carry states eliminated).
//  - Z folded into the S*xb gather leaves; duals straight off xb.
//  - tail: ns = scale*d; xb = fma(2, ns, zmsd); zmsd = z - ns.
// No prologue: y6=0, YIp=1, xb=x0 makes loop iter 1 == reference step 1.

#define NTHREADS 32
#define PDHG_ITERS 150

#define TAU  0.18898223650461357f   /* 1/sqrt(28) */
#define SGM  0.18898223650461357f   /* sigma = tau */
#define TCC  1.8898223650461357f    /* tau * control_strength(10) */

typedef unsigned long long u64;

__device__ __forceinline__ u64 pk(float a, float b) {
    u64 r; asm("mov.b64 %0, {%1, %2};" : "=l"(r) : "f"(a), "f"(b)); return r;
}
__device__ __forceinline__ void upk(float& a, float& b, u64 p) {
    asm("mov.b64 {%0, %1}, %2;" : "=f"(a), "=f"(b) : "l"(p));
}
__device__ __forceinline__ u64 fma2(u64 a, u64 b, u64 c) {
    u64 d; asm("fma.rn.f32x2 %0, %1, %2, %3;" : "=l"(d) : "l"(a), "l"(b), "l"(c)); return d;
}

__device__ __forceinline__ float fast_rsqrt(float v) {
    float r; asm("rsqrt.approx.f32 %0, %1;" : "=f"(r) : "f"(v)); return r;
}
__device__ __forceinline__ float fast_tanh(float x) {
    float e = __expf(2.0f * x);
    return 1.0f - __fdividef(2.0f, e + 1.0f);
}

__global__ __launch_bounds__(NTHREADS)
void matchnet_kernel(
    const float* __restrict__ X,
    const float* __restrict__ W1, const float* __restrict__ b1,
    const float* __restrict__ W2, const float* __restrict__ b2,
    const float* __restrict__ W3, const float* __restrict__ b3,
    const float* __restrict__ W4, const float* __restrict__ b4,
    float* __restrict__ out, int B)
{
    __shared__ __align__(16) float sW1[120], sW2[400], sW3[400], sW4[160];
    __shared__ __align__(16) float sb1[20], sb2[20], sb3[20], sb4[8];

    const int t = threadIdx.x;
    for (int i = t; i < 120; i += NTHREADS) sW1[i] = W1[i];
    for (int i = t; i < 400; i += NTHREADS) sW2[i] = W2[i];
    for (int i = t; i < 400; i += NTHREADS) sW3[i] = W3[i];
    for (int i = t; i < 160; i += NTHREADS) sW4[i] = W4[i];
    if (t < 20) { sb1[t] = b1[t]; sb2[t] = b2[t]; sb3[t] = b3[t]; }
    if (t < 8)  { sb4[t] = b4[t]; }
    __syncthreads();

    const int row = blockIdx.x * NTHREADS + t;
    if (row >= B) return;

    // ---- input row (RHS b of the LP) ----
    float Z0, Z1, Z2, Z3, Z4, Z5;
    {
        const float2* p = (const float2*)(X + row * 6);
        float2 a0 = p[0], a1 = p[1], a2 = p[2];
        Z0 = a0.x; Z1 = a0.y; Z2 = a1.x;
        Z3 = a1.y; Z4 = a2.x; Z5 = a2.y;
    }

    // ---- MLP, f32x2-packed (validated R6/R7) ----
    float h[20], h2[20];
    {
        float Zv[6] = {Z0, Z1, Z2, Z3, Z4, Z5};
        u64 a[10];
#pragma unroll
        for (int jp = 0; jp < 10; jp++) a[jp] = *(const u64*)&sb1[2 * jp];
#pragma unroll
        for (int k = 0; k < 6; k++) {
            u64 zz = pk(Zv[k], Zv[k]);
#pragma unroll
            for (int jp = 0; jp < 10; jp++)
                a[jp] = fma2(zz, *(const u64*)&sW1[k * 20 + 2 * jp], a[jp]);
        }
#pragma unroll
        for (int jp = 0; jp < 10; jp++) {
            float s0, s1; upk(s0, s1, a[jp]);
            h[2 * jp] = fast_tanh(s0); h[2 * jp + 1] = fast_tanh(s1);
        }
    }
    {
        u64 a[10];
#pragma unroll
        for (int jp = 0; jp < 10; jp++) a[jp] = *(const u64*)&sb2[2 * jp];
#pragma unroll
        for (int k = 0; k < 20; k++) {
            u64 hh = pk(h[k], h[k]);
#pragma unroll
            for (int jp = 0; jp < 10; jp++)
                a[jp] = fma2(hh, *(const u64*)&sW2[k * 20 + 2 * jp], a[jp]);
        }
#pragma unroll
        for (int jp = 0; jp < 10; jp++) {
            float s0, s1; upk(s0, s1, a[jp]);
            h2[2 * jp] = fast_tanh(s0); h2[2 * jp + 1] = fast_tanh(s1);
        }
    }
    {
        u64 a[10];
#pragma unroll
        for (int jp = 0; jp < 10; jp++) a[jp] = *(const u64*)&sb3[2 * jp];
#pragma unroll
        for (int k = 0; k < 20; k++) {
            u64 hh = pk(h2[k], h2[k]);
#pragma unroll
            for (int jp = 0; jp < 10; jp++)
                a[jp] = fma2(hh, *(const u64*)&sW3[k * 20 + 2 * jp], a[jp]);
        }
#pragma unroll
        for (int jp = 0; jp < 10; jp++) {
            float s0, s1; upk(s0, s1, a[jp]);
            h[2 * jp] = fast_tanh(s0); h[2 * jp + 1] = fast_tanh(s1);
        }
    }
    float z[8];
    {
        u64 a[4];
#pragma unroll
        for (int jp = 0; jp < 4; jp++) a[jp] = *(const u64*)&sb4[2 * jp];
#pragma unroll
        for (int k = 0; k < 20; k++) {
            u64 hh = pk(h[k], h[k]);
#pragma unroll
            for (int jp = 0; jp < 4; jp++)
                a[jp] = fma2(hh, *(const u64*)&sW4[k * 8 + 2 * jp], a[jp]);
        }
#pragma unroll
        for (int jp = 0; jp < 4; jp++) upk(z[2 * jp], z[2 * jp + 1], a[jp]);
    }

    // ---- PDHG state init (no prologue; loop iter 1 == reference step 1) ----
    // x0 = max(z,0); sdn = x0 - z; xb = x0; zmsd = z - sdn; y6 = 0; YIp = 1.
    float sdn0, sdn1, sdn2, sdn3, sdn4, sdn5, sdn6, sdn7;
    float xb0, xb1, xb2, xb3, xb4, xb5, xb6, xb7;
    float zm0, zm1, zm2, zm3, zm4, zm5, zm6, zm7;
    {
        float x00 = fmaxf(z[0], 0.0f), x01 = fmaxf(z[1], 0.0f);
        float x02 = fmaxf(z[2], 0.0f), x03 = fmaxf(z[3], 0.0f);
        float x04 = fmaxf(z[4], 0.0f), x05 = fmaxf(z[5], 0.0f);
        float x06 = fmaxf(z[6], 0.0f), x07 = fmaxf(z[7], 0.0f);
        sdn0 = x00 - z[0]; sdn1 = x01 - z[1]; sdn2 = x02 - z[2]; sdn3 = x03 - z[3];
        sdn4 = x04 - z[4]; sdn5 = x05 - z[5]; sdn6 = x06 - z[6]; sdn7 = x07 - z[7];
        xb0 = x00; xb1 = x01; xb2 = x02; xb3 = x03;
        xb4 = x04; xb5 = x05; xb6 = x06; xb7 = x07;
        zm0 = z[0] - sdn0; zm1 = z[1] - sdn1; zm2 = z[2] - sdn2; zm3 = z[3] - sdn3;
        zm4 = z[4] - sdn4; zm5 = z[5] - sdn5; zm6 = z[6] - sdn6; zm7 = z[7] - sdn7;
    }
    float y0 = 0.f, y1 = 0.f, y2 = 0.f, y3 = 0.f, y4 = 0.f, y5 = 0.f;
    float w0 = 1.f, w1 = 1.f, w2 = 1.f, w3 = 1.f,   // YIp = yI + 1
          w4 = 1.f, w5 = 1.f, w6 = 1.f, w7 = 1.f;

#pragma unroll 2
    for (int it = 0; it < PDHG_ITERS; it++) {
        // ---- s = S*xb - Z (Z folded into gather leaves) ----
        float s0 = (xb0 + xb2) + ((xb5 + xb7) - Z0);
        float s1 = (xb1 + xb3) + (xb4 - Z1);
        float s2 = (xb0 + xb1) + (xb6 - Z2);
        float s3 = (xb2 + xb3) + (xb5 - Z3);
        float s4 = (xb1 + xb2) + ((xb4 + xb7) - Z4);
        float s5 = (xb0 + xb4) + (xb6 - Z5);

        // ---- dual updates ----
        y0 = fmaxf(0.0f, fmaf(SGM, s0, y0));
        y1 = fmaxf(0.0f, fmaf(SGM, s1, y1));
        y2 = fmaxf(0.0f, fmaf(SGM, s2, y2));
        y3 = fmaxf(0.0f, fmaf(SGM, s3, y3));
        y4 = fmaxf(0.0f, fmaf(SGM, s4, y4));
        y5 = fmaxf(0.0f, fmaf(SGM, s5, y5));

        w0 = fmaxf(1.0f, fmaf(-SGM, xb0, w0));
        w1 = fmaxf(1.0f, fmaf(-SGM, xb1, w1));
        w2 = fmaxf(1.0f, fmaf(-SGM, xb2, w2));
        w3 = fmaxf(1.0f, fmaf(-SGM, xb3, w3));
        w4 = fmaxf(1.0f, fmaf(-SGM, xb4, w4));
        w5 = fmaxf(1.0f, fmaf(-SGM, xb5, w5));
        w6 = fmaxf(1.0f, fmaf(-SGM, xb6, w6));
        w7 = fmaxf(1.0f, fmaf(-SGM, xb7, w7));

        // ---- gy = S^T y - YIp  (= true_g - 1) ----
        float q25 = y2 + y5, q04 = y0 + y4, q14 = y1 + y4;
        float gy0 = (y0 + q25) - w0;
        float gy1 = (q14 + y2) - w1;
        float gy2 = (q04 + y3) - w2;
        float gy3 = (y1 + y3) - w3;
        float gy4 = (q14 + y5) - w4;
        float gy5 = (y0 + y3) - w5;
        float gy6 = q25 - w6;
        float gy7 = q04 - w7;

        // ---- d = sdn - tau*gy  (= sd + tau - tau*g, exact) ----
        float d0 = fmaf(-TAU, gy0, sdn0);
        float d1 = fmaf(-TAU, gy1, sdn1);
        float d2 = fmaf(-TAU, gy2, sdn2);
        float d3 = fmaf(-TAU, gy3, sdn3);
        float d4 = fmaf(-TAU, gy4, sdn4);
        float d5 = fmaf(-TAU, gy5, sdn5);
        float d6 = fmaf(-TAU, gy6, sdn6);
        float d7 = fmaf(-TAU, gy7, sdn7);

        // ---- ||d||^2 tree; rsqrt (nn=0 -> rr=inf -> scale=0, exact) ----
        float p0 = fmaf(d0, d0, d1 * d1);
        float p1 = fmaf(d2, d2, d3 * d3);
        float p2 = fmaf(d4, d4, d5 * d5);
        float p3 = fmaf(d6, d6, d7 * d7);
        float nn = (p0 + p1) + (p2 + p3);
        float rr = fast_rsqrt(nn);
        float scale = fmaxf(0.0f, fmaf(-TCC, rr, 1.0f));

        // ---- primal: ns = scale*d; xb = 2*ns + zmsd; zmsd = z - ns ----
        float ns0 = scale * d0, ns1 = scale * d1, ns2 = scale * d2, ns3 = scale * d3;
        float ns4 = scale * d4, ns5 = scale * d5, ns6 = scale * d6, ns7 = scale * d7;

        xb0 = fmaf(2.0f, ns0, zm0); zm0 = z[0] - ns0; sdn0 = ns0;
        xb1 = fmaf(2.0f, ns1, zm1); zm1 = z[1] - ns1; sdn1 = ns1;
        xb2 = fmaf(2.0f, ns2, zm2); zm2 = z[2] - ns2; sdn2 = ns2;
        xb3 = fmaf(2.0f, ns3, zm3); zm3 = z[3] - ns3; sdn3 = ns3;
        xb4 = fmaf(2.0f, ns4, zm4); zm4 = z[4] - ns4; sdn4 = ns4;
        xb5 = fmaf(2.0f, ns5, zm5); zm5 = z[5] - ns5; sdn5 = ns5;
        xb6 = fmaf(2.0f, ns6, zm6); zm6 = z[6] - ns6; sdn6 = ns6;
        xb7 = fmaf(2.0f, ns7, zm7); zm7 = z[7] - ns7; sdn7 = ns7;
    }

    // ---- x = z + sdn ----
    float4* p = (float4*)(out + row * 8);
    p[0] = make_float4(z[0] + sdn0, z[1] + sdn1, z[2] + sdn2, z[3] + sdn3);
    p[1] = make_float4(z[4] + sdn4, z[5] + sdn5, z[6] + sdn6, z[7] + sdn7);
}

extern "C" void kernel_launch(void* const* d_in, const int* in_sizes, int n_in,
                              void* d_out, int out_size) {
    const float* X  = (const float*)d_in[0];
    const float* W1 = (const float*)d_in[1];
    const float* b1 = (const float*)d_in[2];
    const float* W2 = (const float*)d_in[3];
    const float* b2 = (const float*)d_in[4];
    const float* W3 = (const float*)d_in[5];
    const float* b3 = (const float*)d_in[6];
    const float* W4 = (const float*)d_in[7];
    const float* b4 = (const float*)d_in[8];

    const int B = in_sizes[0] / 6;
    const int grid = (B + NTHREADS - 1) / NTHREADS;
    matchnet_kernel<<<grid, NTHREADS>>>(X, W1, b1, W2, b2, W3, b3, W4, b4,
                                        (float*)d_out, B);
}